// round 9
// baseline (speedup 1.0000x reference)
#include <cuda_runtime.h>
#include <cuda_fp16.h>
#include <cstdint>

// Sizes
#define BSZ 512
#define HID 1024
#define NG  4096
#define INP 128
#define SEQ 96
#define NCTA 128           // persistent grid: 2 mtiles x 64 ntiles
#define KCH 16             // K chunks of 64 halfs
#define ATILEH 16384       // halfs per A chunk tile (256 x 64)
#define ATILEB 32768       // bytes per A chunk tile
#define BTILEB 8192        // bytes per B chunk tile (64 x 64 halfs)
#define SM_B 0             // B panel at smem offset 0 (16 x 8192 = 131072)
#define SM_A 131072        // A stages / C staging union
#define SMEM_BYTES (131072 + 3 * ATILEB)   // 229376

// Scratch (__device__ globals; no cudaMalloc allowed)
__device__ __align__(128) __half d_Weff[(size_t)NG * HID];     // [ntile*16+ch][64][64] swizzled
__device__ float d_beff[NG];                                   // permuted linear
__device__ float d_D0[(size_t)BSZ * NG];                       // step-0 correction [b][n']
__device__ float d_u0[BSZ * INP];
__device__ __align__(128) __half d_hbuf[2][(size_t)BSZ * HID]; // [mtile*16+ch][256][64] swizzled
__device__ float d_part[(size_t)SEQ * 64 * BSZ];               // [t][ntile][b]
__device__ unsigned g_ctr;                                     // grid barrier
__device__ unsigned g_gen;

__device__ __forceinline__ float sigm(float x) { return 1.0f / (1.0f + __expf(-x)); }
__device__ __forceinline__ float tanhe(float x) {
    x = fminf(fmaxf(x, -15.f), 15.f);
    float e = __expf(-2.f * x);
    return (1.f - e) / (1.f + e);
}
__device__ __forceinline__ int permrow(int np) { return ((np & 3) << 10) | (np >> 2); }
__device__ __forceinline__ uint32_t sw128(uint32_t o) { return o ^ ((o >> 3) & 0x70); }

__device__ __forceinline__ uint32_t s2u(const void* p) {
    uint32_t a;
    asm("{ .reg .u64 t; cvta.to.shared.u64 t, %1; cvt.u32.u64 %0, t; }" : "=r"(a) : "l"(p));
    return a;
}
__device__ __forceinline__ void bulkcp(uint32_t dst, const void* src, uint32_t bytes, uint32_t mbar) {
    asm volatile(
        "cp.async.bulk.shared::cluster.global.mbarrier::complete_tx::bytes [%0], [%1], %2, [%3];"
        :: "r"(dst), "l"(src), "r"(bytes), "r"(mbar) : "memory");
}
__device__ __forceinline__ void mma16(float* c, const unsigned* a, const unsigned* b) {
    asm volatile(
        "mma.sync.aligned.m16n8k16.row.col.f32.f16.f16.f32 "
        "{%0,%1,%2,%3}, {%4,%5,%6,%7}, {%8,%9}, {%0,%1,%2,%3};"
        : "+f"(c[0]), "+f"(c[1]), "+f"(c[2]), "+f"(c[3])
        : "r"(a[0]), "r"(a[1]), "r"(a[2]), "r"(a[3]), "r"(b[0]), "r"(b[1]));
}
__device__ __forceinline__ unsigned pack_h2(float a, float b) {
    unsigned lo = (unsigned)__half_as_ushort(__float2half_rn(a));
    unsigned hi = (unsigned)__half_as_ushort(__float2half_rn(b));
    return lo | (hi << 16);
}
#define MBINIT(a, n) \
    asm volatile("mbarrier.init.shared.b64 [%0], %1;" :: "r"(a), "r"(n) : "memory")
#define MBEXPECT(a, n) \
    asm volatile("mbarrier.arrive.expect_tx.shared.b64 _, [%0], %1;" :: "r"(a), "r"(n) : "memory")
#define MBWAIT(a, ph) \
    asm volatile("{\n\t.reg .pred P;\n\tWL_%=: mbarrier.try_wait.parity.acquire.cta.shared::cta.b64 P, [%0], %1, 0x989680;\n\t@P bra.uni WD_%=;\n\tbra.uni WL_%=;\n\tWD_%=:\n\t}" \
                 :: "r"(a), "r"((uint32_t)(ph)) : "memory")
#define FPROXY() asm volatile("fence.proxy.async.shared::cta;" ::: "memory")
#define FPROXY_ALL() asm volatile("fence.proxy.async;" ::: "memory")

// ---------------- Precompute kernels ----------------

// W_eff[n'][m] = W_hh[r][m] + sum_k W_ih[r][k]*W_fc[k][m]; store to B tile layout fp16
__global__ void k_weff(const float* __restrict__ Wih, const float* __restrict__ Whh,
                       const float* __restrict__ Wfc) {
    __shared__ float wih_s[4][INP];
    int m = blockIdx.x * 256 + threadIdx.x;   // grid.x = 4
    int npb = blockIdx.y * 4;                 // grid.y = 1024
    for (int idx = threadIdx.x; idx < 4 * INP; idx += 256)
        wih_s[idx >> 7][idx & 127] = Wih[permrow(npb + (idx >> 7)) * INP + (idx & 127)];
    __syncthreads();
    float acc[4];
    #pragma unroll
    for (int i = 0; i < 4; i++) acc[i] = Whh[(size_t)permrow(npb + i) * HID + m];
    for (int k = 0; k < INP; k++) {
        float w = Wfc[k * HID + m];
        #pragma unroll
        for (int i = 0; i < 4; i++) acc[i] += wih_s[i][k] * w;
    }
    int chunk = m >> 6, kc = m & 63;
    #pragma unroll
    for (int i = 0; i < 4; i++) {
        int np = npb + i;
        int tile = (np >> 6) * 16 + chunk;
        uint32_t bo = sw128((uint32_t)((np & 63) * 128 + kc * 2));
        *(__half*)((char*)d_Weff + (size_t)tile * BTILEB + bo) = __float2half_rn(acc[i]);
    }
}

// h0 (fp16, A tile layout)
__global__ void k_state(const float* __restrict__ hid) {
    int i = blockIdx.x * 256 + threadIdx.x;   // grid 2048
    int b = i >> 10, j = i & 1023;
    int tile = (b >> 8) * 16 + (j >> 6);
    uint32_t bo = sw128((uint32_t)((b & 255) * 128 + (j & 63) * 2));
    *(__half*)((char*)d_hbuf[0] + (size_t)tile * ATILEB + bo) = __float2half_rn(hid[i]);
}

// u0[b][k] = x0[b][k] - b_fc[k] - h0[b]·W_fc[k]
__global__ void k_u0(const float* __restrict__ xt, const float* __restrict__ hid,
                     const float* __restrict__ Wfc, const float* __restrict__ bfc) {
    __shared__ float hs[HID];
    int b = blockIdx.x, k = threadIdx.x;
    for (int i = k; i < HID; i += 128) hs[i] = hid[b * HID + i];
    __syncthreads();
    float acc = 0.f;
    const float* w = Wfc + k * HID;
    for (int i = 0; i < HID; i++) acc += hs[i] * w[i];
    d_u0[b * INP + k] = xt[b * INP + k] - bfc[k] - acc;
}

// b_eff[n'] = b_ih[r]+b_hh[r]+W_ih[r]·b_fc
__global__ void k_beff(const float* __restrict__ Wih, const float* __restrict__ bih,
                       const float* __restrict__ bhh, const float* __restrict__ bfc) {
    int np = blockIdx.x * 256 + threadIdx.x;
    int r = permrow(np);
    float acc = bih[r] + bhh[r];
    for (int k = 0; k < INP; k++) acc += Wih[r * INP + k] * bfc[k];
    d_beff[np] = acc;
}

// D0[b][n'] = u0[b]·W_ih[r]
__global__ void k_d0(const float* __restrict__ Wih) {
    __shared__ float us[4][INP];
    int tid = threadIdx.x;
    int bq = blockIdx.y;
    int np = blockIdx.x * 128 + tid;
    #pragma unroll
    for (int i = 0; i < 4; i++) us[i][tid] = d_u0[(bq * 4 + i) * INP + tid];
    __syncthreads();
    int r = permrow(np);
    float a0 = 0, a1 = 0, a2 = 0, a3 = 0;
    for (int k = 0; k < INP; k++) {
        float w = Wih[r * INP + k];
        a0 += us[0][k] * w; a1 += us[1][k] * w; a2 += us[2][k] * w; a3 += us[3][k] * w;
    }
    d_D0[(size_t)(bq * 4 + 0) * NG + np] = a0;
    d_D0[(size_t)(bq * 4 + 1) * NG + np] = a1;
    d_D0[(size_t)(bq * 4 + 2) * NG + np] = a2;
    d_D0[(size_t)(bq * 4 + 3) * NG + np] = a3;
}

// ---------------- Persistent kernel: all 96 steps ----------------
__global__ void __launch_bounds__(256, 1)
k_lstm(const float* __restrict__ cell, const float* __restrict__ Wfc) {
    extern __shared__ char smem[];
    __shared__ __align__(8) unsigned long long mb[4];   // 0..2 A stages, 3 = B
    __shared__ float s_beff[64];
    __shared__ float s_w127[16];

    const int tid = threadIdx.x, lane = tid & 31, wid = tid >> 5;
    const int wm = wid & 3, wn = wid >> 2;        // 4 x 2 warp grid (64M x 32N)
    const int gid = lane >> 2, tig = lane & 3;
    const int cta = blockIdx.x;
    const int mtile = cta >> 6, ntile = cta & 63;
    const int m0 = mtile * 256;

    if (tid < 64) s_beff[tid] = d_beff[ntile * 64 + tid];
    if (tid < 16) s_w127[tid] = Wfc[127 * HID + ntile * 16 + tid];
    if (tid == 0) {
        #pragma unroll
        for (int s = 0; s < 4; s++) MBINIT(s2u(&mb[s]), 1);
        FPROXY();
    }
    __syncthreads();

    // Load resident B panel (128 KB, once)
    if (tid == 0) {
        MBEXPECT(s2u(&mb[3]), 16 * BTILEB);
        bulkcp(s2u(smem + SM_B), d_Weff + (size_t)ntile * 16 * (BTILEB / 2), 16 * BTILEB,
               s2u(&mb[3]));
    }

    // c state in registers (thread = batch row m0+tid, units ntile*16 .. +15)
    float creg[16];
    {
        const float4* cp = (const float4*)(cell + (size_t)(m0 + tid) * HID + ntile * 16);
        #pragma unroll
        for (int q = 0; q < 4; q++) {
            float4 v = cp[q];
            creg[q * 4 + 0] = v.x; creg[q * 4 + 1] = v.y;
            creg[q * 4 + 2] = v.z; creg[q * 4 + 3] = v.w;
        }
    }
    MBWAIT(s2u(&mb[3]), 0);

    float* smC = (float*)(smem + SM_A);    // C staging overlaps A stages (between steps)

    for (int t = 0; t < SEQ; t++) {
        const __half* Asrc = d_hbuf[t & 1] + (size_t)mtile * 16 * ATILEH;

        if (tid == 0) {
            #pragma unroll
            for (int s = 0; s < 3; s++) {
                MBEXPECT(s2u(&mb[s]), ATILEB);
                bulkcp(s2u(smem + SM_A + s * ATILEB), Asrc + s * ATILEH, ATILEB, s2u(&mb[s]));
            }
        }

        float acc[4][4][4];
        #pragma unroll
        for (int a = 0; a < 4; a++)
            #pragma unroll
            for (int b = 0; b < 4; b++)
                #pragma unroll
                for (int c = 0; c < 4; c++) acc[a][b][c] = 0.f;

        for (int c = 0; c < KCH; c++) {
            const int q = c / 3, s = c - 3 * q;            // s = c % 3
            const int ph = ((s ? t : 0) + q) & 1;          // per-stage parity
            MBWAIT(s2u(&mb[s]), ph);

            const unsigned* As = (const unsigned*)(smem + SM_A + s * ATILEB);
            const unsigned* Bs = (const unsigned*)(smem + SM_B + c * BTILEB);
            #pragma unroll
            for (int k8 = 0; k8 < 32; k8 += 8) {
                unsigned a[4][4], b[4][2];
                #pragma unroll
                for (int mf = 0; mf < 4; mf++) {
                    int r = wm * 64 + mf * 16 + gid;
                    int xr = (r & 7) << 2;
                    int c0 = (k8 + tig) ^ xr, c1 = (k8 + tig + 4) ^ xr;
                    a[mf][0] = As[r * 32 + c0];
                    a[mf][1] = As[(r + 8) * 32 + c0];
                    a[mf][2] = As[r * 32 + c1];
                    a[mf][3] = As[(r + 8) * 32 + c1];
                }
                #pragma unroll
                for (int nf = 0; nf < 4; nf++) {
                    int n = wn * 32 + nf * 8 + gid;
                    int xn = (n & 7) << 2;
                    b[nf][0] = Bs[n * 32 + ((k8 + tig) ^ xn)];
                    b[nf][1] = Bs[n * 32 + ((k8 + tig + 4) ^ xn)];
                }
                #pragma unroll
                for (int mf = 0; mf < 4; mf++)
                    #pragma unroll
                    for (int nf = 0; nf < 4; nf++) mma16(acc[mf][nf], a[mf], b[nf]);
            }
            __syncthreads();
            if (tid == 0 && c + 3 < KCH) {
                MBEXPECT(s2u(&mb[s]), ATILEB);
                bulkcp(s2u(smem + SM_A + s * ATILEB), Asrc + (c + 3) * ATILEH, ATILEB,
                       s2u(&mb[s]));
            }
        }

        // dump C tile (256 x 64, stride 66)
        #pragma unroll
        for (int mf = 0; mf < 4; mf++)
            #pragma unroll
            for (int nf = 0; nf < 4; nf++) {
                int row = wm * 64 + mf * 16 + gid;
                int col = wn * 32 + nf * 8 + 2 * tig;
                *(float2*)&smC[row * 66 + col]       = make_float2(acc[mf][nf][0], acc[mf][nf][1]);
                *(float2*)&smC[(row + 8) * 66 + col] = make_float2(acc[mf][nf][2], acc[mf][nf][3]);
            }
        __syncthreads();

        // fused LSTM epilogue: thread = batch row
        {
            const float* myc = smC + tid * 66;
            const float4* d0p = (const float4*)(d_D0 + (size_t)(m0 + tid) * NG + ntile * 64);
            const bool is0 = (t == 0);
            float part = 0.f;
            unsigned hp[8];
            #pragma unroll
            for (int u2 = 0; u2 < 8; u2++) {
                float hv2[2];
                #pragma unroll
                for (int v = 0; v < 2; v++) {
                    int u = u2 * 2 + v;
                    float2 p0 = *(const float2*)(myc + 4 * u);
                    float2 p1 = *(const float2*)(myc + 4 * u + 2);
                    float gi = p0.x + s_beff[4 * u];
                    float gf = p0.y + s_beff[4 * u + 1];
                    float gg = p1.x + s_beff[4 * u + 2];
                    float go = p1.y + s_beff[4 * u + 3];
                    if (is0) {
                        float4 dd = d0p[u];
                        gi += dd.x; gf += dd.y; gg += dd.z; go += dd.w;
                    }
                    float cn = sigm(gf) * creg[u] + sigm(gi) * tanhe(gg);
                    float hv = sigm(go) * tanhe(cn);
                    creg[u] = cn;
                    part += hv * s_w127[u];
                    hv2[v] = hv;
                }
                hp[u2] = pack_h2(hv2[0], hv2[1]);
            }
            // h -> next-step A layout (fp16 swizzled). NOTE: swizzle is non-linear,
            // second 16B block goes to sw ^ 16 (NOT sw + 16).
            char* hT = (char*)(d_hbuf[(t + 1) & 1]) + (size_t)(mtile * 16 + (ntile >> 2)) * ATILEB;
            uint32_t bo = (uint32_t)(tid * 128 + (ntile & 3) * 32);
            uint32_t sw = bo ^ ((bo >> 3) & 0x70);
            *(uint4*)(hT + sw)        = make_uint4(hp[0], hp[1], hp[2], hp[3]);
            *(uint4*)(hT + (sw ^ 16)) = make_uint4(hp[4], hp[5], hp[6], hp[7]);
            d_part[((size_t)t * 64 + ntile) * BSZ + m0 + tid] = part;
        }

        // publish generic-proxy h stores to the async proxy (next step's bulk copies),
        // then grid barrier
        FPROXY_ALL();
        __threadfence();
        __syncthreads();
        if (tid == 0) {
            unsigned g = *((volatile unsigned*)&g_gen);
            if (atomicAdd(&g_ctr, 1u) == NCTA - 1) {
                atomicExch(&g_ctr, 0u);
                __threadfence();
                atomicExch(&g_gen, g + 1u);
            } else {
                while (*((volatile unsigned*)&g_gen) == g) { }
                __threadfence();
            }
        }
        __syncthreads();
    }
}

// out[b][t] = b_fc[127] + sum over 64 tiles
__global__ void k_reduce(float* __restrict__ out, const float* __restrict__ bfc) {
    int idx = blockIdx.x * 256 + threadIdx.x;
    if (idx >= BSZ * SEQ) return;
    int b = idx / SEQ, t = idx % SEQ;
    float s = bfc[127];
    #pragma unroll 8
    for (int nt = 0; nt < 64; nt++) s += d_part[((size_t)t * 64 + nt) * BSZ + b];
    out[idx] = s;
}

extern "C" void kernel_launch(void* const* d_in, const int* in_sizes, int n_in,
                              void* d_out, int out_size) {
    const float* xt   = (const float*)d_in[0];
    const float* hid  = (const float*)d_in[1];
    const float* cell = (const float*)d_in[2];
    const float* Wih  = (const float*)d_in[3];
    const float* Whh  = (const float*)d_in[4];
    const float* bih  = (const float*)d_in[5];
    const float* bhh  = (const float*)d_in[6];
    const float* Wfc  = (const float*)d_in[7];
    const float* bfc  = (const float*)d_in[8];
    float* out = (float*)d_out;

    cudaFuncSetAttribute(k_lstm, cudaFuncAttributeMaxDynamicSharedMemorySize, SMEM_BYTES);

    k_weff<<<dim3(4, 1024), 256>>>(Wih, Whh, Wfc);
    k_state<<<2048, 256>>>(hid);
    k_u0<<<512, 128>>>(xt, hid, Wfc, bfc);
    k_beff<<<16, 256>>>(Wih, bih, bhh, bfc);
    k_d0<<<dim3(32, 128), 128>>>(Wih);
    k_lstm<<<NCTA, 256, SMEM_BYTES>>>(cell, Wfc);
    k_reduce<<<192, 256>>>(out, bfc);
}